// round 15
// baseline (speedup 1.0000x reference)
#include <cuda_runtime.h>
#include <cuda_fp16.h>
#include <stdint.h>
#include <math.h>

#define BV 16
#define CV 128
#define HV 128
#define WV 128

#define A_TILE 32768           // packed A: [kstep 8][mtile 8][lane 32][16B] fp16
#define B_TILE 34816           // packed B: [kstep 8][pxi 136][32B] fp16
#define NPX 136                // pixel rows incl. halo (pxi = w+1, w in [-1,134])

__device__ float g_smax[BV];
__device__ float g_wmax[CV];
// Pre-packed fp16 A tiles: [b][tap 0..8], each 32KB, HMMA-fragment packed
__device__ unsigned char g_wa[(size_t)BV * 9 * A_TILE];

// ---------------- helpers ----------------
__device__ __forceinline__ uint32_t smem_u32(const void* p) {
    uint32_t a;
    asm("{ .reg .u64 t; cvta.to.shared.u64 t, %1; cvt.u32.u64 %0, t; }" : "=r"(a) : "l"(p));
    return a;
}
// A fragment packing (mma.m16n8k16 A frag, row-major M x K)
__device__ __forceinline__ uint32_t addrA(int o, int ic) {
    int kstep = ic >> 4, kk = ic & 15, mt = o >> 4;
    int lane = ((o & 7) << 2) | ((kk & 7) >> 1);
    int reg = ((kk >> 3) << 1) | ((o >> 3) & 1);
    return (uint32_t)(((kstep * 8 + mt) * 32 + lane) * 16 + reg * 4 + (kk & 1) * 2);
}

__device__ __forceinline__ void mma_f16(float* c, const uint32_t* a, const uint32_t* b2) {
    asm volatile(
        "mma.sync.aligned.m16n8k16.row.col.f32.f16.f16.f32 "
        "{%0,%1,%2,%3}, {%4,%5,%6,%7}, {%8,%9}, {%0,%1,%2,%3};"
        : "+f"(c[0]), "+f"(c[1]), "+f"(c[2]), "+f"(c[3])
        : "r"(a[0]), "r"(a[1]), "r"(a[2]), "r"(a[3]), "r"(b2[0]), "r"(b2[1]));
}

// ---------------- Kernel 1: per-sample style inf-norm ----------------
__global__ void k_smax(const float* __restrict__ style) {
    int b = blockIdx.x, t = threadIdx.x;
    float m = 0.f;
    for (int i = t; i < CV; i += 32) m = fmaxf(m, fabsf(style[b * CV + i]));
    #pragma unroll
    for (int o = 16; o; o >>= 1) m = fmaxf(m, __shfl_xor_sync(0xffffffffu, m, o));
    if (t == 0) g_smax[b] = m;
}

// ---------------- Kernel 2: per-out-channel weight inf-norm ----------------
__global__ void k_wmax(const float* __restrict__ weight) {
    int o = blockIdx.x, t = threadIdx.x;
    const float* wp = weight + (size_t)o * CV * 9;
    float m = 0.f;
    for (int i = t; i < CV * 9; i += 128) m = fmaxf(m, fabsf(wp[i]));
    __shared__ float red[4];
    #pragma unroll
    for (int off = 16; off; off >>= 1) m = fmaxf(m, __shfl_xor_sync(0xffffffffu, m, off));
    if ((t & 31) == 0) red[t >> 5] = m;
    __syncthreads();
    if (t == 0) g_wmax[o] = fmaxf(fmaxf(red[0], red[1]), fmaxf(red[2], red[3]));
}

// ---------------- Kernel 3: modulate+demodulate -> packed fp16 A tiles ----------------
__global__ void k_mod(const float* __restrict__ style, const float* __restrict__ weight) {
    int o = blockIdx.x, b = blockIdx.y, i = threadIdx.x;
    float s = style[b * CV + i] / g_smax[b];
    float scale = (1.0f / sqrtf((float)(CV * 9))) / g_wmax[o] * s;
    const float* wp = weight + ((size_t)o * CV + i) * 9;
    float v[9];
    float ss = 0.f;
    #pragma unroll
    for (int k = 0; k < 9; k++) { v[k] = wp[k] * scale; ss += v[k] * v[k]; }
    __shared__ float red[4];
    #pragma unroll
    for (int off = 16; off; off >>= 1) ss += __shfl_xor_sync(0xffffffffu, ss, off);
    if ((i & 31) == 0) red[i >> 5] = ss;
    __syncthreads();
    float coe = rsqrtf(red[0] + red[1] + red[2] + red[3] + 1e-8f);
    uint32_t off = addrA(o, i);
    #pragma unroll
    for (int k = 0; k < 9; k++) {
        __half hv = __float2half_rn(v[k] * coe);
        unsigned char* base = g_wa + (size_t)(b * 9 + k) * A_TILE;   // tap = ky*3+kx
        *(unsigned short*)(base + off) = __half_as_ushort(hv);
    }
}

// ---------------- Kernel 4: fp16 HMMA implicit-GEMM conv ----------------
// CTA = (h, b). 8 warps = 2(M) x 4(N). Warp: 64 oc x 32 px.
// A fragments straight from g_wa via LDG (L1-resident, shared with co-resident CTA).
#define DYN_SMEM (B_TILE)   // 34816 B
__global__ __launch_bounds__(256, 2) void k_conv(const float* __restrict__ x,
                                                 float* __restrict__ out) {
    extern __shared__ unsigned char sm[];
    unsigned char* Bs = sm;

    int h = blockIdx.x, b = blockIdx.y;
    int tid = threadIdx.x, wid = tid >> 5, lane = tid & 31;
    int warp_m = wid >> 2, warp_n = wid & 3;

    float c[4][4][4];
    #pragma unroll
    for (int mi = 0; mi < 4; mi++)
        #pragma unroll
        for (int ni = 0; ni < 4; ni++)
            #pragma unroll
            for (int r = 0; r < 4; r++) c[mi][ni][r] = 0.f;

    uint32_t Bbase = smem_u32(Bs);

    for (int ky = 0; ky < 3; ky++) {
        int hh = h + ky - 1;
        if ((unsigned)hh >= HV) continue;

        __syncthreads();   // previous taps done reading B
        // ---- stage B row hh: per (kstep, pxi) one contiguous 32B block
        // ushort order within block: 0,1,8,9, 2,3,10,11, 4,5,12,13, 6,7,14,15
        {
            const float* xrow = x + ((size_t)(b * CV) * HV + hh) * WV;
            for (int it = tid; it < 8 * NPX; it += 256) {
                int ks = it / NPX, pxi = it % NPX;
                int w = pxi - 1;
                bool valid = (unsigned)w < WV;
                const float* xp = xrow + (size_t)(ks * 16) * HV * WV + (valid ? w : 0);
                unsigned short hs[16];
                #pragma unroll
                for (int j = 0; j < 16; j++) {
                    float f = valid ? xp[(size_t)j * HV * WV] : 0.f;
                    int pos = (((j & 7) >> 1) << 2) | ((j >> 3) << 1) | (j & 1);
                    hs[pos] = __half_as_ushort(__float2half_rn(f));
                }
                uint32_t boff = (uint32_t)(ks * NPX + pxi) * 32;
                *(uint4*)(Bs + boff)      = *(uint4*)&hs[0];
                *(uint4*)(Bs + boff + 16) = *(uint4*)&hs[8];
            }
        }
        __syncthreads();   // B published

        #pragma unroll
        for (int kx = 0; kx < 3; kx++) {
            const unsigned char* Ah = g_wa + (size_t)(b * 9 + ky * 3 + kx) * A_TILE;
            int pxr = warp_n * 32 + (lane >> 2) + kx;   // shifted pixel row
            #pragma unroll
            for (int ks = 0; ks < 8; ks++) {
                uint32_t bf[4][2];
                #pragma unroll
                for (int ni = 0; ni < 4; ni++) {
                    uint32_t bo = (uint32_t)((ks * NPX + pxr + ni * 8) * 4 + (lane & 3)) * 8;
                    asm volatile("ld.shared.v2.u32 {%0,%1}, [%2];"
                                 : "=r"(bf[ni][0]), "=r"(bf[ni][1]) : "r"(Bbase + bo));
                }
                #pragma unroll
                for (int mi = 0; mi < 4; mi++) {
                    uint32_t ao = (uint32_t)((ks * 8 + warp_m * 4 + mi) * 32 + lane) * 16;
                    uint4 av = __ldg((const uint4*)(Ah + ao));
                    uint32_t af[4] = { av.x, av.y, av.z, av.w };
                    #pragma unroll
                    for (int ni = 0; ni < 4; ni++)
                        mma_f16(c[mi][ni], af, bf[ni]);
                }
            }
        }
    }

    // ---- epilogue: C regs -> out, 8B stores ----
    #pragma unroll
    for (int mi = 0; mi < 4; mi++) {
        #pragma unroll
        for (int ni = 0; ni < 4; ni++) {
            int oc = warp_m * 64 + mi * 16 + (lane >> 2);
            int px = warp_n * 32 + ni * 8 + (lane & 3) * 2;
            float* op = out + ((size_t)(b * CV + oc) * HV + h) * WV + px;
            *(float2*)op = make_float2(c[mi][ni][0], c[mi][ni][1]);
            *(float2*)(op + (size_t)8 * HV * WV) = make_float2(c[mi][ni][2], c[mi][ni][3]);
        }
    }
}

extern "C" void kernel_launch(void* const* d_in, const int* in_sizes, int n_in,
                              void* d_out, int out_size) {
    const float* x      = (const float*)d_in[0];  // (16,128,128,128)
    const float* style  = (const float*)d_in[1];  // (16,128)
    const float* weight = (const float*)d_in[2];  // (128,128,3,3)
    float* out = (float*)d_out;                   // (16,128,128,128)

    cudaFuncSetAttribute(k_conv, cudaFuncAttributeMaxDynamicSharedMemorySize, DYN_SMEM);

    k_smax<<<16, 32>>>(style);
    k_wmax<<<128, 128>>>(weight);
    k_mod<<<dim3(128, 16), 128>>>(style, weight);
    k_conv<<<dim3(HV, BV), 256, DYN_SMEM>>>(x, out);
}

// round 16
// speedup vs baseline: 1.0018x; 1.0018x over previous
#include <cuda_runtime.h>
#include <cuda_fp16.h>
#include <stdint.h>
#include <math.h>

#define BV 16
#define CV 128
#define HV 128
#define WV 128

#define A_TILE 32768           // packed A: [kstep 8][mtile 8][lane 32][16B] fp16
#define B_TILE 34816           // packed B: [kstep 8][pxi 136][32B] fp16
#define NPX 136                // pixel rows incl. halo (pxi = w+1, w in [-1,134])

__device__ float g_smax[BV];
__device__ float g_wmax[CV];
// Pre-packed fp16 A tiles: [b][tap 0..8], each 32KB, HMMA-fragment packed
__device__ unsigned char g_wa[(size_t)BV * 9 * A_TILE];

// ---------------- helpers ----------------
__device__ __forceinline__ uint32_t smem_u32(const void* p) {
    uint32_t a;
    asm("{ .reg .u64 t; cvta.to.shared.u64 t, %1; cvt.u32.u64 %0, t; }" : "=r"(a) : "l"(p));
    return a;
}
// A fragment packing (mma.m16n8k16 A frag, row-major M x K)
__device__ __forceinline__ uint32_t addrA(int o, int ic) {
    int kstep = ic >> 4, kk = ic & 15, mt = o >> 4;
    int lane = ((o & 7) << 2) | ((kk & 7) >> 1);
    int reg = ((kk >> 3) << 1) | ((o >> 3) & 1);
    return (uint32_t)(((kstep * 8 + mt) * 32 + lane) * 16 + reg * 4 + (kk & 1) * 2);
}

__device__ __forceinline__ void mma_f16(float* c, const uint32_t* a, const uint32_t* b2) {
    asm volatile(
        "mma.sync.aligned.m16n8k16.row.col.f32.f16.f16.f32 "
        "{%0,%1,%2,%3}, {%4,%5,%6,%7}, {%8,%9}, {%0,%1,%2,%3};"
        : "+f"(c[0]), "+f"(c[1]), "+f"(c[2]), "+f"(c[3])
        : "r"(a[0]), "r"(a[1]), "r"(a[2]), "r"(a[3]), "r"(b2[0]), "r"(b2[1]));
}

// ---------------- Kernel 1: per-sample style inf-norm ----------------
__global__ void k_smax(const float* __restrict__ style) {
    int b = blockIdx.x, t = threadIdx.x;
    float m = 0.f;
    for (int i = t; i < CV; i += 32) m = fmaxf(m, fabsf(style[b * CV + i]));
    #pragma unroll
    for (int o = 16; o; o >>= 1) m = fmaxf(m, __shfl_xor_sync(0xffffffffu, m, o));
    if (t == 0) g_smax[b] = m;
}

// ---------------- Kernel 2: per-out-channel weight inf-norm ----------------
__global__ void k_wmax(const float* __restrict__ weight) {
    int o = blockIdx.x, t = threadIdx.x;
    const float* wp = weight + (size_t)o * CV * 9;
    float m = 0.f;
    for (int i = t; i < CV * 9; i += 128) m = fmaxf(m, fabsf(wp[i]));
    __shared__ float red[4];
    #pragma unroll
    for (int off = 16; off; off >>= 1) m = fmaxf(m, __shfl_xor_sync(0xffffffffu, m, off));
    if ((t & 31) == 0) red[t >> 5] = m;
    __syncthreads();
    if (t == 0) g_wmax[o] = fmaxf(fmaxf(red[0], red[1]), fmaxf(red[2], red[3]));
}

// ---------------- Kernel 3: modulate+demodulate -> packed fp16 A tiles ----------------
__global__ void k_mod(const float* __restrict__ style, const float* __restrict__ weight) {
    int o = blockIdx.x, b = blockIdx.y, i = threadIdx.x;
    float s = style[b * CV + i] / g_smax[b];
    float scale = (1.0f / sqrtf((float)(CV * 9))) / g_wmax[o] * s;
    const float* wp = weight + ((size_t)o * CV + i) * 9;
    float v[9];
    float ss = 0.f;
    #pragma unroll
    for (int k = 0; k < 9; k++) { v[k] = wp[k] * scale; ss += v[k] * v[k]; }
    __shared__ float red[4];
    #pragma unroll
    for (int off = 16; off; off >>= 1) ss += __shfl_xor_sync(0xffffffffu, ss, off);
    if ((i & 31) == 0) red[i >> 5] = ss;
    __syncthreads();
    float coe = rsqrtf(red[0] + red[1] + red[2] + red[3] + 1e-8f);
    uint32_t off = addrA(o, i);
    #pragma unroll
    for (int k = 0; k < 9; k++) {
        __half hv = __float2half_rn(v[k] * coe);
        unsigned char* base = g_wa + (size_t)(b * 9 + k) * A_TILE;   // tap = ky*3+kx
        *(unsigned short*)(base + off) = __half_as_ushort(hv);
    }
}

// ---------------- Kernel 4: fp16 HMMA implicit-GEMM conv ----------------
// CTA = (h, b). 8 warps = 2(M) x 4(N). Warp: 64 oc x 32 px.
// A fragments straight from g_wa via LDG (L1-resident, shared with co-resident CTA).
#define DYN_SMEM (B_TILE)   // 34816 B
__global__ __launch_bounds__(256, 2) void k_conv(const float* __restrict__ x,
                                                 float* __restrict__ out) {
    extern __shared__ unsigned char sm[];
    unsigned char* Bs = sm;

    int h = blockIdx.x, b = blockIdx.y;
    int tid = threadIdx.x, wid = tid >> 5, lane = tid & 31;
    int warp_m = wid >> 2, warp_n = wid & 3;

    float c[4][4][4];
    #pragma unroll
    for (int mi = 0; mi < 4; mi++)
        #pragma unroll
        for (int ni = 0; ni < 4; ni++)
            #pragma unroll
            for (int r = 0; r < 4; r++) c[mi][ni][r] = 0.f;

    uint32_t Bbase = smem_u32(Bs);

    for (int ky = 0; ky < 3; ky++) {
        int hh = h + ky - 1;
        if ((unsigned)hh >= HV) continue;

        __syncthreads();   // previous taps done reading B
        // ---- stage B row hh: per (kstep, pxi) one contiguous 32B block
        // ushort order within block: 0,1,8,9, 2,3,10,11, 4,5,12,13, 6,7,14,15
        {
            const float* xrow = x + ((size_t)(b * CV) * HV + hh) * WV;
            for (int it = tid; it < 8 * NPX; it += 256) {
                int ks = it / NPX, pxi = it % NPX;
                int w = pxi - 1;
                bool valid = (unsigned)w < WV;
                const float* xp = xrow + (size_t)(ks * 16) * HV * WV + (valid ? w : 0);
                unsigned short hs[16];
                #pragma unroll
                for (int j = 0; j < 16; j++) {
                    float f = valid ? xp[(size_t)j * HV * WV] : 0.f;
                    int pos = (((j & 7) >> 1) << 2) | ((j >> 3) << 1) | (j & 1);
                    hs[pos] = __half_as_ushort(__float2half_rn(f));
                }
                uint32_t boff = (uint32_t)(ks * NPX + pxi) * 32;
                *(uint4*)(Bs + boff)      = *(uint4*)&hs[0];
                *(uint4*)(Bs + boff + 16) = *(uint4*)&hs[8];
            }
        }
        __syncthreads();   // B published

        #pragma unroll
        for (int kx = 0; kx < 3; kx++) {
            const unsigned char* Ah = g_wa + (size_t)(b * 9 + ky * 3 + kx) * A_TILE;
            int pxr = warp_n * 32 + (lane >> 2) + kx;   // shifted pixel row
            #pragma unroll
            for (int ks = 0; ks < 8; ks++) {
                uint32_t bf[4][2];
                #pragma unroll
                for (int ni = 0; ni < 4; ni++) {
                    uint32_t bo = (uint32_t)((ks * NPX + pxr + ni * 8) * 4 + (lane & 3)) * 8;
                    asm volatile("ld.shared.v2.u32 {%0,%1}, [%2];"
                                 : "=r"(bf[ni][0]), "=r"(bf[ni][1]) : "r"(Bbase + bo));
                }
                #pragma unroll
                for (int mi = 0; mi < 4; mi++) {
                    uint32_t ao = (uint32_t)((ks * 8 + warp_m * 4 + mi) * 32 + lane) * 16;
                    uint4 av = __ldg((const uint4*)(Ah + ao));
                    uint32_t af[4] = { av.x, av.y, av.z, av.w };
                    #pragma unroll
                    for (int ni = 0; ni < 4; ni++)
                        mma_f16(c[mi][ni], af, bf[ni]);
                }
            }
        }
    }

    // ---- epilogue: C regs -> out, 8B stores ----
    #pragma unroll
    for (int mi = 0; mi < 4; mi++) {
        #pragma unroll
        for (int ni = 0; ni < 4; ni++) {
            int oc = warp_m * 64 + mi * 16 + (lane >> 2);
            int px = warp_n * 32 + ni * 8 + (lane & 3) * 2;
            float* op = out + ((size_t)(b * CV + oc) * HV + h) * WV + px;
            *(float2*)op = make_float2(c[mi][ni][0], c[mi][ni][1]);
            *(float2*)(op + (size_t)8 * HV * WV) = make_float2(c[mi][ni][2], c[mi][ni][3]);
        }
    }
}

extern "C" void kernel_launch(void* const* d_in, const int* in_sizes, int n_in,
                              void* d_out, int out_size) {
    const float* x      = (const float*)d_in[0];  // (16,128,128,128)
    const float* style  = (const float*)d_in[1];  // (16,128)
    const float* weight = (const float*)d_in[2];  // (128,128,3,3)
    float* out = (float*)d_out;                   // (16,128,128,128)

    cudaFuncSetAttribute(k_conv, cudaFuncAttributeMaxDynamicSharedMemorySize, DYN_SMEM);

    k_smax<<<16, 32>>>(style);
    k_wmax<<<128, 128>>>(weight);
    k_mod<<<dim3(128, 16), 128>>>(style, weight);
    k_conv<<<dim3(HV, BV), 256, DYN_SMEM>>>(x, out);
}